// round 17
// baseline (speedup 1.0000x reference)
#include <cuda_runtime.h>
#include <cfloat>
#include <cstdint>

#define Bn  8
#define Ls  3136      // 56*56
#define Cn  64
#define HID 32
#define KN  30
#define NV  (Bn*Ls)   // 25088 global vertices/edges
#define NS  256       // sample columns per row (every 12th)
#define MW  392       // mask bytes per row (Ls/8) = 98 u32
#define CAP2 512      // candidate capacity

// ---------------- device scratch (static globals; no allocations) ----------------
__device__ float    g_sq  [NV];
__device__ float    g_d2  [(size_t)Bn*Ls*Ls];   // 314.7 MB distance matrices
__device__ float    g_sd2 [(size_t)NV*NS];      // sampled distances (25.7 MB)
__device__ float    g_thrA[NV];                 // 8th smallest sample
__device__ float    g_thrB[NV];                 // 16th smallest sample (fallback)
__device__ unsigned char g_mask[(size_t)NV*MW]; // 9.8 MB candidate bitmask
__device__ int      g_nbr [(size_t)NV*KN];
__device__ int      g_dvi [NV];
__device__ int      g_off [NV];
__device__ int      g_cnt [NV];
__device__ int      g_adj [(size_t)NV*KN];
__device__ float    g_h1  [(size_t)NV*HID];
__device__ float    g_y1  [(size_t)NV*HID];
__device__ float    g_h2  [(size_t)NV*Cn];
__device__ float    g_y2  [(size_t)NV*Cn];

#define BN_SCALE 0.99999500003749969f
#define FLIPU(u) ((u) ^ ((unsigned)(((int)(u)) >> 31) | 0x80000000u))

__device__ __forceinline__ float unflip_f(unsigned v) {
    unsigned m = ((int)v < 0) ? 0x80000000u : 0xffffffffu;
    return __uint_as_float(v ^ m);
}

// ---------------- kernel 1: row squared norms + zero counters ----------------
__global__ void sq_kernel(const float* __restrict__ x) {
    int tid = threadIdx.x;
    int gv = blockIdx.x * 8 + (tid >> 5);
    int lane = tid & 31;
    const float* p = x + (size_t)gv * Cn;
    float a = p[lane] * p[lane] + p[lane + 32] * p[lane + 32];
    #pragma unroll
    for (int off = 16; off; off >>= 1) a += __shfl_down_sync(0xffffffffu, a, off);
    if (lane == 0) g_sq[gv] = a;
    int t = blockIdx.x * 256 + tid;
    if (t < NV) { g_cnt[t] = 0; g_dvi[t] = 0; }
}

// ---------------- kernel 2: sampled distances (rows x 256 sample cols) --------------
__global__ void __launch_bounds__(64) sample_kernel(const float* __restrict__ x) {
    int s = blockIdx.z;
    int sB = s * Ls;
    const float* A  = x + (size_t)sB * Cn;
    const float* sq = g_sq + sB;
    int i0 = blockIdx.y << 6, q0 = blockIdx.x << 6;

    __shared__ __align__(16) float Ast[64][68];
    __shared__ __align__(16) float Bst[64][68];
    int tid = threadIdx.x;

    for (int f = tid; f < 1024; f += 64) {
        int m = f >> 4, kq = (f & 15) << 2;
        float4 av = *(const float4*)(A + (size_t)(i0 + m) * Cn + kq);
        Ast[kq + 0][m] = av.x; Ast[kq + 1][m] = av.y; Ast[kq + 2][m] = av.z; Ast[kq + 3][m] = av.w;
        float4 bv = *(const float4*)(A + (size_t)(12 * (q0 + m)) * Cn + kq);
        Bst[kq + 0][m] = bv.x; Bst[kq + 1][m] = bv.y; Bst[kq + 2][m] = bv.z; Bst[kq + 3][m] = bv.w;
    }
    __syncthreads();

    int m0 = (tid >> 3) << 3;
    int n0 = (tid & 7) << 3;
    float acc[8][8];
    #pragma unroll
    for (int r = 0; r < 8; r++)
        #pragma unroll
        for (int c = 0; c < 8; c++) acc[r][c] = 0.f;

    #pragma unroll 8
    for (int k = 0; k < 64; k++) {
        float a[8], b[8];
        *(float4*)(a)     = *(const float4*)&Ast[k][m0];
        *(float4*)(a + 4) = *(const float4*)&Ast[k][m0 + 4];
        *(float4*)(b)     = *(const float4*)&Bst[k][n0];
        *(float4*)(b + 4) = *(const float4*)&Bst[k][n0 + 4];
        #pragma unroll
        for (int r = 0; r < 8; r++)
            #pragma unroll
            for (int c = 0; c < 8; c++) acc[r][c] = fmaf(a[r], b[c], acc[r][c]);
    }

    float sqi[8], sqj[8];
    #pragma unroll
    for (int r = 0; r < 8; r++) sqi[r] = sq[i0 + m0 + r];
    #pragma unroll
    for (int c = 0; c < 8; c++) sqj[c] = sq[12 * (q0 + n0 + c)];
    #pragma unroll
    for (int r = 0; r < 8; r++) {
        float* orow = g_sd2 + (size_t)(sB + i0 + m0 + r) * NS + q0 + n0;
        #pragma unroll
        for (int c = 0; c < 8; c++) orow[c] = sqi[r] + sqj[c] - 2.f * acc[r][c];
    }
}

// ---------------- kernel 3: per-row thresholds (8th and 16th smallest sample) --------
__global__ void __launch_bounds__(256) thrsel_kernel() {
    int gv = blockIdx.x * 8 + (threadIdx.x >> 5);
    int lane = threadIdx.x & 31;
    const float* srow = g_sd2 + (size_t)gv * NS;
    unsigned v[8];
    #pragma unroll
    for (int j = 0; j < 8; j++) v[j] = FLIPU(__float_as_uint(srow[lane + 32 * j]));
    #pragma unroll 1
    for (int r = 0; r < 16; r++) {
        unsigned long long m = ~0ull;
        #pragma unroll
        for (int j = 0; j < 8; j++) {
            unsigned long long p = ((unsigned long long)v[j] << 13) | (unsigned)(lane << 3) | (unsigned)j;
            m = (p < m) ? p : m;
        }
        #pragma unroll
        for (int o = 16; o; o >>= 1) {
            unsigned long long t2 = __shfl_down_sync(0xffffffffu, m, o);
            m = (t2 < m) ? t2 : m;
        }
        m = __shfl_sync(0xffffffffu, m, 0);
        if ((int)((m >> 3) & 31u) == lane) v[m & 7u] = 0xffffffffu;
        if (lane == 0 && r == 7)  g_thrA[gv] = unflip_f((unsigned)(m >> 13));
        if (lane == 0 && r == 15) g_thrB[gv] = unflip_f((unsigned)(m >> 13));
    }
}

// ---------------- kernel 4: d2 + candidate bitmask (128 threads, 8x4 micro-tile) ------
__global__ void __launch_bounds__(128) dist_kernel(const float* __restrict__ x) {
    int ti = blockIdx.y, tj = blockIdx.x;
    if (ti > tj) return;
    int s = blockIdx.z;
    int sB = s * Ls;
    const float* A  = x + (size_t)sB * Cn;
    float*       D  = g_d2 + (size_t)s * Ls * Ls;
    const float* sq = g_sq + sB;
    int i0 = ti << 6, j0 = tj << 6;

    __shared__ __align__(16) float Ast[64][68];
    __shared__ __align__(16) float Bst[64][68];
    int tid = threadIdx.x;   // 128 threads

    for (int f = tid; f < 1024; f += 128) {
        int m = f >> 4, kq = (f & 15) << 2;
        float4 av = *(const float4*)(A + (size_t)(i0 + m) * Cn + kq);
        Ast[kq + 0][m] = av.x; Ast[kq + 1][m] = av.y; Ast[kq + 2][m] = av.z; Ast[kq + 3][m] = av.w;
        float4 bv = *(const float4*)(A + (size_t)(j0 + m) * Cn + kq);
        Bst[kq + 0][m] = bv.x; Bst[kq + 1][m] = bv.y; Bst[kq + 2][m] = bv.z; Bst[kq + 3][m] = bv.w;
    }
    __syncthreads();

    int m0 = (tid >> 4) << 3;   // 8 row-groups of 8
    int n0 = (tid & 15) << 2;   // 16 col-groups of 4
    float acc[8][4];
    #pragma unroll
    for (int r = 0; r < 8; r++)
        #pragma unroll
        for (int c = 0; c < 4; c++) acc[r][c] = 0.f;

    #pragma unroll 8
    for (int k = 0; k < 64; k++) {
        float a[8], b[4];
        *(float4*)(a)     = *(const float4*)&Ast[k][m0];
        *(float4*)(a + 4) = *(const float4*)&Ast[k][m0 + 4];
        *(float4*)(b)     = *(const float4*)&Bst[k][n0];
        #pragma unroll
        for (int r = 0; r < 8; r++)
            #pragma unroll
            for (int c = 0; c < 4; c++) acc[r][c] = fmaf(a[r], b[c], acc[r][c]);
    }

    float sqj[4], sqi[8], thri[8], thrj[4];
    #pragma unroll
    for (int c = 0; c < 4; c++) { sqj[c] = sq[j0 + n0 + c]; thrj[c] = g_thrA[sB + j0 + n0 + c]; }
    #pragma unroll
    for (int r = 0; r < 8; r++) { sqi[r] = sq[i0 + m0 + r]; thri[r] = g_thrA[sB + i0 + m0 + r]; }
    #pragma unroll
    for (int r = 0; r < 8; r++)
        #pragma unroll
        for (int c = 0; c < 4; c++) acc[r][c] = sqi[r] + sqj[c] - 2.f * acc[r][c];

    // d2 stores (row view)
    #pragma unroll
    for (int r = 0; r < 8; r++) {
        float* drow = D + (size_t)(i0 + m0 + r) * Ls + j0 + n0;
        *(float4*)(drow) = make_float4(acc[r][0], acc[r][1], acc[r][2], acc[r][3]);
    }

    // row-view mask: nibble per thread, pair (tid, tid^1) combines into one byte
    #pragma unroll
    for (int r = 0; r < 8; r++) {
        unsigned nib = 0;
        #pragma unroll
        for (int c = 0; c < 4; c++) nib |= (acc[r][c] <= thri[r]) ? (1u << c) : 0u;
        unsigned other = __shfl_xor_sync(0xffffffffu, nib, 1);
        if (!(tid & 1))
            g_mask[(size_t)(sB + i0 + m0 + r) * MW + ((j0 + n0) >> 3)] =
                (unsigned char)(nib | (other << 4));
    }

    if (ti != tj) {
        // transposed d2 stores
        #pragma unroll
        for (int c = 0; c < 4; c++) {
            float* drow = D + (size_t)(j0 + n0 + c) * Ls + i0 + m0;
            *(float4*)(drow)     = make_float4(acc[0][c], acc[1][c], acc[2][c], acc[3][c]);
            *(float4*)(drow + 4) = make_float4(acc[4][c], acc[5][c], acc[6][c], acc[7][c]);
        }
        // col-view mask: byte covers 8 rows (m0..m0+7), one per col
        #pragma unroll
        for (int c = 0; c < 4; c++) {
            unsigned byte = 0;
            #pragma unroll
            for (int r = 0; r < 8; r++) byte |= (acc[r][c] <= thrj[c]) ? (1u << r) : 0u;
            g_mask[(size_t)(sB + j0 + n0 + c) * MW + ((i0 + m0) >> 3)] = (unsigned char)byte;
        }
    }
}

// ---------------- kernel 5: mask -> gather d2 candidates -> exact top-30 ----------
__global__ void __launch_bounds__(128) select_kernel() {
    int s = blockIdx.y, i = blockIdx.x;
    int sB = s * Ls;
    int gv = sB + i;
    int tid = threadIdx.x;   // 128
    const float* row = g_d2 + (size_t)gv * Ls;

    __shared__ unsigned long long cand[CAP2];   // 4 KB
    __shared__ unsigned fb[Ls];                 // 12.5 KB (final fallback keys)
    __shared__ int scnt;
    if (tid == 0) scnt = 0;
    __syncthreads();

    int* nout = g_nbr + (size_t)gv * KN;
    int* dv = g_dvi + sB;

    // phase 1: mask-driven gather (expected ~98 candidates)
    const unsigned* mrow = (const unsigned*)(g_mask + (size_t)gv * MW);
    if (tid < MW / 4) {
        unsigned m = mrow[tid];
        while (m) {
            int b = __ffs(m) - 1; m &= m - 1;
            int j = tid * 32 + b;
            float d = row[j];
            int p = atomicAdd(&scnt, 1);
            if (p < CAP2) cand[p] = ((unsigned long long)FLIPU(__float_as_uint(d)) << 32) | (unsigned)j;
        }
    }
    __syncthreads();
    int cnt = scnt;

    if (cnt >= KN && cnt <= CAP2) {
        for (int t = tid; t < cnt; t += 128) {
            unsigned long long K = cand[t];
            int r = 0;
            #pragma unroll 4
            for (int j = 0; j < cnt; j++) r += (cand[j] < K);
            if (r < KN) {
                int idx = (int)(K & 0xffffffffull);
                nout[r] = idx;
                atomicAdd(&dv[idx], 1);
            }
        }
        return;
    }

    // phase 2 (~1% of rows): stream d2 row with looser 16th-sample threshold
    float tB = g_thrB[gv];
    __syncthreads();
    if (tid == 0) scnt = 0;
    __syncthreads();
    for (int t = tid; t < Ls; t += 128) {
        float d = row[t];
        unsigned u = FLIPU(__float_as_uint(d));
        fb[t] = u;
        if (d <= tB) {
            int p = atomicAdd(&scnt, 1);
            if (p < CAP2) cand[p] = ((unsigned long long)u << 32) | (unsigned)t;
        }
    }
    __syncthreads();
    cnt = scnt;
    if (cnt >= KN && cnt <= CAP2) {
        for (int t = tid; t < cnt; t += 128) {
            unsigned long long K = cand[t];
            int r = 0;
            for (int j = 0; j < cnt; j++) r += (cand[j] < K);
            if (r < KN) {
                int idx = (int)(K & 0xffffffffull);
                nout[r] = idx;
                atomicAdd(&dv[idx], 1);
            }
        }
        return;
    }

    // final exact fallback: full-row rank select over fb
    for (int t = tid; t < Ls; t += 128) {
        unsigned ut = fb[t];
        int r = 0;
        for (int j = 0; j < Ls; j++) {
            unsigned uj = fb[j];
            r += (uj < ut) || (uj == ut && j < t);
        }
        if (r < KN) {
            nout[r] = t;
            atomicAdd(&dv[t], 1);
        }
    }
}

// ---------------- kernel 6: exclusive scan of degrees (shuffle-based) ----------------
__global__ void scan_kernel() {
    __shared__ int wsum[32];
    int tid = threadIdx.x;    // 1024
    int lane = tid & 31, w = tid >> 5;
    int start = tid * 25;
    int sum = 0;
    for (int t = start; t < start + 25 && t < NV; t++) sum += g_dvi[t];
    int v = sum;
    #pragma unroll
    for (int o = 1; o < 32; o <<= 1) {
        int n = __shfl_up_sync(0xffffffffu, v, o);
        if (lane >= o) v += n;
    }
    if (lane == 31) wsum[w] = v;
    __syncthreads();
    if (w == 0) {
        int sv = wsum[lane];
        #pragma unroll
        for (int o = 1; o < 32; o <<= 1) {
            int n = __shfl_up_sync(0xffffffffu, sv, o);
            if (lane >= o) sv += n;
        }
        wsum[lane] = sv;
    }
    __syncthreads();
    int excl = v - sum + ((w > 0) ? wsum[w - 1] : 0);
    for (int t = start; t < start + 25 && t < NV; t++) {
        g_off[t] = excl;
        excl += g_dvi[t];
    }
}

// ---------------- kernel 7: CSR fill (warp per edge) ----------------
__global__ void fill_kernel() {
    int s = blockIdx.y;
    int e = blockIdx.x * 8 + (threadIdx.x >> 5);
    int lane = threadIdx.x & 31;
    int ge = s * Ls + e;
    if (lane < KN) {
        int v  = g_nbr[(size_t)ge * KN + lane];
        int gv = s * Ls + v;
        int pos = atomicAdd(&g_cnt[gv], 1);
        g_adj[g_off[gv] + pos] = ge;
    }
}

// ---------------- kernel 8: theta1 + BN ----------------
__global__ void theta1_kernel(const float* __restrict__ x, const float* __restrict__ w1,
                              const float* __restrict__ b1, const float* __restrict__ g1,
                              const float* __restrict__ be1) {
    __shared__ float ws[Cn * HID];
    int tid = threadIdx.x;
    for (int t = tid; t < Cn * HID; t += 256) ws[t] = w1[t];
    __syncthreads();
    int gv = blockIdx.x * 8 + (tid >> 5);
    int lane = tid & 31;
    const float* f = x + (size_t)gv * Cn;
    float f0 = f[lane], f1 = f[lane + 32];
    float acc = 0.f;
    #pragma unroll
    for (int c = 0; c < 32; c++) acc = fmaf(__shfl_sync(0xffffffffu, f0, c), ws[c * HID + lane], acc);
    #pragma unroll
    for (int c = 0; c < 32; c++) acc = fmaf(__shfl_sync(0xffffffffu, f1, c), ws[(c + 32) * HID + lane], acc);
    g_h1[(size_t)gv * HID + lane] = (acc + b1[lane]) * (g1[lane] * BN_SCALE) + be1[lane];
}

// ---------------- kernel 9: v2e mean, conv1 ----------------
__global__ void v2e1_kernel() {
    int s = blockIdx.y;
    int e = blockIdx.x * 8 + (threadIdx.x >> 5);
    int lane = threadIdx.x & 31;
    int ge = s * Ls + e;
    const int* nb = g_nbr + (size_t)ge * KN;
    int myn = (lane < KN) ? nb[lane] : 0;
    const float* h = g_h1 + (size_t)s * Ls * HID;
    float acc = 0.f;
    #pragma unroll
    for (int j = 0; j < KN; j++) {
        int v = __shfl_sync(0xffffffffu, myn, j);
        acc += h[(size_t)v * HID + lane];
    }
    g_y1[(size_t)ge * HID + lane] = acc * (1.f / KN);
}

// ---------------- kernel 10: e2v mean + relu + theta2 + BN (fused) ----------------
__global__ void __launch_bounds__(256) e2v1t2_kernel(const float* __restrict__ w2,
                                                     const float* __restrict__ b2,
                                                     const float* __restrict__ g2,
                                                     const float* __restrict__ be2) {
    __shared__ float ws[HID * Cn];
    int tid = threadIdx.x;
    for (int t = tid; t < HID * Cn; t += 256) ws[t] = w2[t];
    __syncthreads();
    int gv = blockIdx.x * 8 + (tid >> 5);
    int lane = tid & 31;
    int cnt = g_dvi[gv];
    int off = g_off[gv];
    float acc = 0.f;
    for (int t = 0; t < cnt; t++) {
        int ge = g_adj[off + t];
        acc += g_y1[(size_t)ge * HID + lane];
    }
    float d = fmaxf((float)cnt, 1.f);
    float o = fmaxf(acc / d, 0.f);
    float a0 = 0.f, a1 = 0.f;
    #pragma unroll
    for (int c = 0; c < 32; c++) {
        float in = __shfl_sync(0xffffffffu, o, c);
        a0 = fmaf(in, ws[c * Cn + lane], a0);
        a1 = fmaf(in, ws[c * Cn + lane + 32], a1);
    }
    g_h2[(size_t)gv * Cn + lane]      = (a0 + b2[lane])      * (g2[lane]      * BN_SCALE) + be2[lane];
    g_h2[(size_t)gv * Cn + lane + 32] = (a1 + b2[lane + 32]) * (g2[lane + 32] * BN_SCALE) + be2[lane + 32];
}

// ---------------- kernel 11: v2e mean, conv2 ----------------
__global__ void v2e2_kernel() {
    int s = blockIdx.y;
    int e = blockIdx.x * 8 + (threadIdx.x >> 5);
    int lane = threadIdx.x & 31;
    int ge = s * Ls + e;
    const int* nb = g_nbr + (size_t)ge * KN;
    int myn = (lane < KN) ? nb[lane] : 0;
    const float* h = g_h2 + (size_t)s * Ls * Cn;
    float a0 = 0.f, a1 = 0.f;
    #pragma unroll
    for (int j = 0; j < KN; j++) {
        int v = __shfl_sync(0xffffffffu, myn, j);
        const float* hv = h + (size_t)v * Cn;
        a0 += hv[lane];
        a1 += hv[lane + 32];
    }
    g_y2[(size_t)ge * Cn + lane]      = a0 * (1.f / KN);
    g_y2[(size_t)ge * Cn + lane + 32] = a1 * (1.f / KN);
}

// ---------------- kernel 12: e2v mean, conv2 -> output ----------------
__global__ void e2v2_kernel(float* __restrict__ out) {
    int gv = blockIdx.x * 8 + (threadIdx.x >> 5);
    int lane = threadIdx.x & 31;
    int cnt = g_dvi[gv];
    int off = g_off[gv];
    float a0 = 0.f, a1 = 0.f;
    for (int t = 0; t < cnt; t++) {
        int ge = g_adj[off + t];
        const float* y = g_y2 + (size_t)ge * Cn;
        a0 += y[lane];
        a1 += y[lane + 32];
    }
    float d = fmaxf((float)cnt, 1.f);
    out[(size_t)gv * Cn + lane]      = a0 / d;
    out[(size_t)gv * Cn + lane + 32] = a1 / d;
}

// ---------------- launch ----------------
extern "C" void kernel_launch(void* const* d_in, const int* in_sizes, int n_in,
                              void* d_out, int out_size) {
    const float* x   = (const float*)d_in[0];
    const float* w1  = (const float*)d_in[1];
    const float* b1  = (const float*)d_in[2];
    const float* g1  = (const float*)d_in[3];
    const float* be1 = (const float*)d_in[4];
    const float* w2  = (const float*)d_in[5];
    const float* b2  = (const float*)d_in[6];
    const float* g2  = (const float*)d_in[7];
    const float* be2 = (const float*)d_in[8];
    float* out = (float*)d_out;

    sq_kernel<<<NV / 8, 256>>>(x);
    sample_kernel<<<dim3(NS / 64, Ls / 64, Bn), 64>>>(x);
    thrsel_kernel<<<NV / 8, 256>>>();
    dist_kernel<<<dim3(Ls / 64, Ls / 64, Bn), 128>>>(x);
    select_kernel<<<dim3(Ls, Bn), 128>>>();
    scan_kernel<<<1, 1024>>>();
    fill_kernel<<<dim3(Ls / 8, Bn), 256>>>();
    theta1_kernel<<<NV / 8, 256>>>(x, w1, b1, g1, be1);
    v2e1_kernel<<<dim3(Ls / 8, Bn), 256>>>();
    e2v1t2_kernel<<<NV / 8, 256>>>(w2, b2, g2, be2);
    v2e2_kernel<<<dim3(Ls / 8, Bn), 256>>>();
    e2v2_kernel<<<NV / 8, 256>>>(out);
}